// round 5
// baseline (speedup 1.0000x reference)
#include <cuda_runtime.h>
#include <cstdint>

#define B_TOTAL 65536
#define TLEN 200
#define NSTEP 101
#define TPB 128

typedef unsigned long long u64;

__device__ float g_y0[B_TOTAL * 6];

// ---------------- f32x2 helpers ----------------
__device__ __forceinline__ u64 pack_dup(float v) {
    u64 r; asm("mov.b64 %0, {%1, %2};" : "=l"(r) : "f"(v), "f"(v)); return r;
}
__device__ __forceinline__ void unpack2(u64 v, float& lo, float& hi) {
    asm("mov.b64 {%0, %1}, %2;" : "=f"(lo), "=f"(hi) : "l"(v));
}
__device__ __forceinline__ u64 ffma2(u64 a, u64 b, u64 c) {
    u64 d; asm("fma.rn.f32x2 %0, %1, %2, %3;" : "=l"(d) : "l"(a), "l"(b), "l"(c)); return d;
}
__device__ __forceinline__ unsigned smem_addr(const void* p) {
    return (unsigned)__cvta_generic_to_shared(p);
}
__device__ __forceinline__ void lds2(unsigned a, u64& x, u64& y) {
    asm("ld.shared.v2.u64 {%0, %1}, [%2];" : "=l"(x), "=l"(y) : "r"(a));
}
__device__ __forceinline__ u64 lds1(unsigned a) {
    u64 x; asm("ld.shared.u64 %0, [%1];" : "=l"(x) : "r"(a)); return x;
}

// Load 13 b64 (26 floats) from a 16B-aligned row slice: 6x v2.u64 + 1x u64.
__device__ __forceinline__ void load13(unsigned a, u64 w[13]) {
    lds2(a,      w[0],  w[1]);
    lds2(a + 16, w[2],  w[3]);
    lds2(a + 32, w[4],  w[5]);
    lds2(a + 48, w[6],  w[7]);
    lds2(a + 64, w[8],  w[9]);
    lds2(a + 80, w[10], w[11]);
    w[12] = lds1(a + 96);
}

struct SAddrs {
    unsigned w1;   // + half*112 + d*224
    unsigned b1;   // + half*112
    unsigned w2o;  // own-input rows,  own output cols
    unsigned w2p;  // partner rows,    own output cols
    unsigned b2;   // + half*112
    unsigned w3;   // + (half*26 + j)*32
};

// ---------------- MLP for ONE sample, THIS thread owns one 26-unit half ----------------
// Returns full k[6] (identical on both lanes of the pair).
__device__ __forceinline__ void mlp_half(const float yt[6], float k[6],
                                         const SAddrs s, const float bb3[6]) {
    // ---- layer 1: own half of h1 ----
    u64 h[13];
    load13(s.b1, h);
    #pragma unroll
    for (int d = 0; d < 6; d++) {
        u64 yd = pack_dup(yt[d]);
        u64 w[13];
        load13(s.w1 + d * 224, w);
        #pragma unroll
        for (int p = 0; p < 13; p++) h[p] = ffma2(yd, w[p], h[p]);
    }
    // ReLU -> own scalars
    float mo[26];
    #pragma unroll
    for (int p = 0; p < 13; p++) {
        float x, z;
        unpack2(h[p], x, z);
        mo[2 * p]     = fmaxf(x, 0.0f);
        mo[2 * p + 1] = fmaxf(z, 0.0f);
    }

    // ---- layer 2: own half of h2, summing own inputs then partner inputs ----
    u64 g[13];
    load13(s.b2, g);
    #pragma unroll
    for (int j = 0; j < 26; j++) {
        u64 m = pack_dup(mo[j]);
        u64 w[13];
        load13(s.w2o + j * 224, w);
        #pragma unroll
        for (int p = 0; p < 13; p++) g[p] = ffma2(m, w[p], g[p]);
    }
    #pragma unroll
    for (int j = 0; j < 26; j++) {
        float mpj = __shfl_xor_sync(0xffffffffu, mo[j], 1);
        u64 m = pack_dup(mpj);
        u64 w[13];
        load13(s.w2p + j * 224, w);
        #pragma unroll
        for (int p = 0; p < 13; p++) g[p] = ffma2(m, w[p], g[p]);
    }
    // ReLU -> own h2 scalars (reuse mo)
    #pragma unroll
    for (int p = 0; p < 13; p++) {
        float x, z;
        unpack2(g[p], x, z);
        mo[2 * p]     = fmaxf(x, 0.0f);
        mo[2 * p + 1] = fmaxf(z, 0.0f);
    }

    // ---- layer 3: partial k over own 26 h2 units ----
    u64 o0 = 0ull, o1 = 0ull, o2 = 0ull;
    #pragma unroll
    for (int j = 0; j < 26; j++) {
        u64 m = pack_dup(mo[j]);
        unsigned r = s.w3 + j * 32;
        u64 w0, w1;
        lds2(r, w0, w1);
        u64 w2v = lds1(r + 16);
        o0 = ffma2(m, w0, o0);
        o1 = ffma2(m, w1, o1);
        o2 = ffma2(m, w2v, o2);
    }
    float kp[6];
    unpack2(o0, kp[0], kp[1]);
    unpack2(o1, kp[2], kp[3]);
    unpack2(o2, kp[4], kp[5]);
    #pragma unroll
    for (int d = 0; d < 6; d++) {
        // commutative add -> bit-identical on both lanes of the pair
        k[d] = (kp[d] + __shfl_xor_sync(0xffffffffu, kp[d], 1)) + bb3[d];
    }
}

// ---------------- Phase A: y0 = mean over T (warp per sample) ----------------
__global__ void mean_kernel(const float* __restrict__ x0) {
    const unsigned w = (blockIdx.x * blockDim.x + threadIdx.x) >> 5;
    const int lane = threadIdx.x & 31;
    if (w >= B_TOTAL) return;
    const float2* p = reinterpret_cast<const float2*>(x0) + (size_t)w * 600u;
    float sx = 0.0f, sy = 0.0f;
    if (lane < 30) {
        #pragma unroll
        for (int kk = 0; kk < 20; kk++) {
            float2 v = __ldg(p + lane + 30 * kk);
            sx += v.x;
            sy += v.y;
        }
    }
    const int c = lane % 3;
    float v0 = (c == 0) ? sx : 0.0f, v1 = (c == 0) ? sy : 0.0f;
    float v2 = (c == 1) ? sx : 0.0f, v3 = (c == 1) ? sy : 0.0f;
    float v4 = (c == 2) ? sx : 0.0f, v5 = (c == 2) ? sy : 0.0f;
    #pragma unroll
    for (int o = 16; o; o >>= 1) {
        v0 += __shfl_xor_sync(0xffffffffu, v0, o);
        v1 += __shfl_xor_sync(0xffffffffu, v1, o);
        v2 += __shfl_xor_sync(0xffffffffu, v2, o);
        v3 += __shfl_xor_sync(0xffffffffu, v3, o);
        v4 += __shfl_xor_sync(0xffffffffu, v4, o);
        v5 += __shfl_xor_sync(0xffffffffu, v5, o);
    }
    if (lane == 0) {
        const float inv = 1.0f / (float)TLEN;
        float* o = g_y0 + (size_t)w * 6u;
        o[0] = v0 * inv; o[1] = v1 * inv; o[2] = v2 * inv;
        o[3] = v3 * inv; o[4] = v4 * inv; o[5] = v5 * inv;
    }
}

// ---------------- Phase B: RK4, one sample per LANE PAIR ----------------
// Shared layouts (all half-slices 16B aligned):
//   sW1[6][2][28]   : sW1[d][h][j] = W1[d][h*26+j]
//   sW2[52][2][28]  : sW2[i][h][j] = W2[i][h*26+j]   (rows 50,51 zero)
//   sW3[52][8]      : sW3[i][c]    = W3[i][c]        (rows 50,51 zero)
//   sB1h[2][28], sB2h[2][28]
__global__ void __launch_bounds__(TPB, 4) ode_kernel(
    const float* __restrict__ t_span,
    const float* __restrict__ W1, const float* __restrict__ b1,
    const float* __restrict__ W2, const float* __restrict__ b2,
    const float* __restrict__ W3, const float* __restrict__ b3,
    float* __restrict__ out) {
    __shared__ __align__(16) float sW1[6 * 56];
    __shared__ __align__(16) float sW2[52 * 56];
    __shared__ __align__(16) float sW3[52 * 8];
    __shared__ __align__(16) float sB1h[56];
    __shared__ __align__(16) float sB2h[56];
    __shared__ __align__(16) float sTs[NSTEP + 1];

    const int t = threadIdx.x;
    // zero (pads + virtual rows must be exactly 0.0f)
    for (int i = t; i < 6 * 56; i += TPB) sW1[i] = 0.0f;
    for (int i = t; i < 52 * 56; i += TPB) sW2[i] = 0.0f;
    for (int i = t; i < 52 * 8; i += TPB) sW3[i] = 0.0f;
    if (t < 56) { sB1h[t] = 0.0f; sB2h[t] = 0.0f; }
    __syncthreads();
    // scatter real weights into half-padded layout
    for (int i = t; i < 6 * 50; i += TPB) {
        int d = i / 50, c = i % 50;
        sW1[d * 56 + (c / 26) * 28 + (c % 26)] = W1[i];
    }
    for (int i = t; i < 50 * 50; i += TPB) {
        int r = i / 50, c = i % 50;
        sW2[r * 56 + (c / 26) * 28 + (c % 26)] = W2[i];
    }
    for (int i = t; i < 50 * 6; i += TPB) {
        int r = i / 6, c = i % 6;
        sW3[r * 8 + c] = W3[i];
    }
    if (t < 50) {
        sB1h[(t / 26) * 28 + (t % 26)] = b1[t];
        sB2h[(t / 26) * 28 + (t % 26)] = b2[t];
    }
    for (int i = t; i < NSTEP + 1; i += TPB) sTs[i] = t_span[i];
    __syncthreads();

    const int half = t & 1;
    const int gid = (blockIdx.x * TPB + t) >> 1;  // sample id

    SAddrs s;
    const unsigned colOff = (unsigned)half * 112u;
    s.w1  = smem_addr(sW1)  + colOff;
    s.b1  = smem_addr(sB1h) + colOff;
    s.b2  = smem_addr(sB2h) + colOff;
    s.w2o = smem_addr(sW2) + colOff + (unsigned)(half * 26) * 224u;
    s.w2p = smem_addr(sW2) + colOff + (unsigned)((half ^ 1) * 26) * 224u;
    s.w3  = smem_addr(sW3) + (unsigned)half * 832u;  // 26 rows * 32B

    float bb3[6];
    #pragma unroll
    for (int d = 0; d < 6; d++) bb3[d] = b3[d];

    float y[6];
    #pragma unroll
    for (int d = 0; d < 6; d++) y[d] = g_y0[gid * 6 + d];

    float yt[6], k[6], acc[6];

    #pragma unroll 1
    for (int stp = 0; stp < NSTEP; stp++) {
        const float dt = sTs[stp + 1] - sTs[stp];
        #pragma unroll
        for (int d = 0; d < 6; d++) yt[d] = y[d];
        #pragma unroll 1
        for (int st = 0; st < 4; st++) {
            mlp_half(yt, k, s, bb3);
            if (st == 0) {
                #pragma unroll
                for (int d = 0; d < 6; d++) { acc[d] = k[d]; yt[d] = fmaf(0.5f * dt, k[d], y[d]); }
            } else if (st == 1) {
                #pragma unroll
                for (int d = 0; d < 6; d++) { acc[d] += 2.0f * k[d]; yt[d] = fmaf(0.5f * dt, k[d], y[d]); }
            } else if (st == 2) {
                #pragma unroll
                for (int d = 0; d < 6; d++) { acc[d] += 2.0f * k[d]; yt[d] = fmaf(dt, k[d], y[d]); }
            } else {
                #pragma unroll
                for (int d = 0; d < 6; d++) y[d] = fmaf(dt * (1.0f / 6.0f), acc[d] + k[d], y[d]);
            }
        }
    }

    if (half == 0) {
        #pragma unroll
        for (int d = 0; d < 6; d++) out[gid * 6 + d] = y[d];
    }
}

extern "C" void kernel_launch(void* const* d_in, const int* in_sizes, int n_in,
                              void* d_out, int out_size) {
    const float* x0 = (const float*)d_in[0];
    const float* ts = (const float*)d_in[1];
    const float* W1 = (const float*)d_in[2];
    const float* b1 = (const float*)d_in[3];
    const float* W2 = (const float*)d_in[4];
    const float* b2 = (const float*)d_in[5];
    const float* W3 = (const float*)d_in[6];
    const float* b3 = (const float*)d_in[7];
    float* out = (float*)d_out;

    mean_kernel<<<8192, 256>>>(x0);
    // 2 threads per sample -> 131072 threads
    ode_kernel<<<(B_TOTAL * 2) / TPB, TPB>>>(ts, W1, b1, W2, b2, W3, b3, out);
}

// round 6
// speedup vs baseline: 4.1014x; 4.1014x over previous
#include <cuda_runtime.h>
#include <cstdint>

#define B_TOTAL 65536
#define TLEN 200
#define NSTEP 101
#define TPB 128          // 4 warps = 2 warp-pairs = 64 samples per block

typedef unsigned long long u64;

__device__ float g_y0[B_TOTAL * 6];

// ---------------- f32x2 helpers ----------------
__device__ __forceinline__ u64 pack_dup(float v) {
    u64 r; asm("mov.b64 %0, {%1, %2};" : "=l"(r) : "f"(v), "f"(v)); return r;
}
__device__ __forceinline__ void unpack2(u64 v, float& lo, float& hi) {
    asm("mov.b64 {%0, %1}, %2;" : "=f"(lo), "=f"(hi) : "l"(v));
}
__device__ __forceinline__ u64 ffma2(u64 a, u64 b, u64 c) {
    u64 d; asm("fma.rn.f32x2 %0, %1, %2, %3;" : "=l"(d) : "l"(a), "l"(b), "l"(c)); return d;
}
__device__ __forceinline__ unsigned smem_addr(const void* p) {
    return (unsigned)__cvta_generic_to_shared(p);
}
__device__ __forceinline__ void lds2(unsigned a, u64& x, u64& y) {
    asm("ld.shared.v2.u64 {%0, %1}, [%2];" : "=l"(x), "=l"(y) : "r"(a));
}
__device__ __forceinline__ u64 lds1(unsigned a) {
    u64 x; asm("ld.shared.u64 %0, [%1];" : "=l"(x) : "r"(a)); return x;
}
__device__ __forceinline__ float ldsf(unsigned a) {
    float x; asm("ld.shared.f32 %0, [%1];" : "=f"(x) : "r"(a)); return x;
}
__device__ __forceinline__ void stsf(unsigned a, float v) {
    asm volatile("st.shared.f32 [%0], %1;" :: "r"(a), "f"(v));
}
__device__ __forceinline__ void pair_bar(int id) {
    asm volatile("bar.sync %0, 64;" :: "r"(id) : "memory");
}

// Load 13 b64 (26 floats) from a 16B-aligned slice.
__device__ __forceinline__ void load13(unsigned a, u64 w[13]) {
    lds2(a,      w[0],  w[1]);
    lds2(a + 16, w[2],  w[3]);
    lds2(a + 32, w[4],  w[5]);
    lds2(a + 48, w[6],  w[7]);
    lds2(a + 64, w[8],  w[9]);
    lds2(a + 80, w[10], w[11]);
    w[12] = lds1(a + 96);
}

// ---------------- Phase A: y0 = mean over T (warp per sample) ----------------
__global__ void mean_kernel(const float* __restrict__ x0) {
    const unsigned w = (blockIdx.x * blockDim.x + threadIdx.x) >> 5;
    const int lane = threadIdx.x & 31;
    if (w >= B_TOTAL) return;
    const float2* p = reinterpret_cast<const float2*>(x0) + (size_t)w * 600u;
    float sx = 0.0f, sy = 0.0f;
    if (lane < 30) {
        #pragma unroll
        for (int kk = 0; kk < 20; kk++) {
            float2 v = __ldg(p + lane + 30 * kk);
            sx += v.x;
            sy += v.y;
        }
    }
    const int c = lane % 3;
    float v0 = (c == 0) ? sx : 0.0f, v1 = (c == 0) ? sy : 0.0f;
    float v2 = (c == 1) ? sx : 0.0f, v3 = (c == 1) ? sy : 0.0f;
    float v4 = (c == 2) ? sx : 0.0f, v5 = (c == 2) ? sy : 0.0f;
    #pragma unroll
    for (int o = 16; o; o >>= 1) {
        v0 += __shfl_xor_sync(0xffffffffu, v0, o);
        v1 += __shfl_xor_sync(0xffffffffu, v1, o);
        v2 += __shfl_xor_sync(0xffffffffu, v2, o);
        v3 += __shfl_xor_sync(0xffffffffu, v3, o);
        v4 += __shfl_xor_sync(0xffffffffu, v4, o);
        v5 += __shfl_xor_sync(0xffffffffu, v5, o);
    }
    if (lane == 0) {
        const float inv = 1.0f / (float)TLEN;
        float* o = g_y0 + (size_t)w * 6u;
        o[0] = v0 * inv; o[1] = v1 * inv; o[2] = v2 * inv;
        o[3] = v3 * inv; o[4] = v4 * inv; o[5] = v5 * inv;
    }
}

// ---------------- Phase B: RK4, one sample per LANE, hidden dim split across a WARP PAIR ----
// Shared layouts (halves at float offsets 0 / 28, all 16B aligned):
//   sW1[6][56], sW2[50][56], sW3[52][8] (rows 50,51 zero), sB1h[56], sB2h[56]
//   sH[pair][lane*57 + i]  : h1 exchange (i in 0..51, stride 57 -> conflict-free)
//   sK[pair][half][lane*9 + c] : partial-k exchange
__global__ void __launch_bounds__(TPB, 4) ode_kernel(
    const float* __restrict__ t_span,
    const float* __restrict__ W1, const float* __restrict__ b1,
    const float* __restrict__ W2, const float* __restrict__ b2,
    const float* __restrict__ W3, const float* __restrict__ b3,
    float* __restrict__ out) {
    __shared__ __align__(16) float sW1[6 * 56];
    __shared__ __align__(16) float sW2[50 * 56];
    __shared__ __align__(16) float sW3[52 * 8];
    __shared__ __align__(16) float sB1h[56];
    __shared__ __align__(16) float sB2h[56];
    __shared__ __align__(16) float sTs[NSTEP + 1];
    __shared__ __align__(16) float sH[2 * 32 * 57];
    __shared__ __align__(16) float sK[2 * 2 * 32 * 9];

    const int t = threadIdx.x;
    // zero pads + virtual rows
    for (int i = t; i < 6 * 56; i += TPB) sW1[i] = 0.0f;
    for (int i = t; i < 50 * 56; i += TPB) sW2[i] = 0.0f;
    for (int i = t; i < 52 * 8; i += TPB) sW3[i] = 0.0f;
    if (t < 56) { sB1h[t] = 0.0f; sB2h[t] = 0.0f; }
    __syncthreads();
    for (int i = t; i < 6 * 50; i += TPB) {
        int d = i / 50, c = i % 50;
        sW1[d * 56 + (c / 26) * 28 + (c % 26)] = W1[i];
    }
    for (int i = t; i < 50 * 50; i += TPB) {
        int r = i / 50, c = i % 50;
        sW2[r * 56 + (c / 26) * 28 + (c % 26)] = W2[i];
    }
    for (int i = t; i < 50 * 6; i += TPB) {
        int r = i / 6, c = i % 6;
        sW3[r * 8 + c] = W3[i];
    }
    if (t < 50) {
        sB1h[(t / 26) * 28 + (t % 26)] = b1[t];
        sB2h[(t / 26) * 28 + (t % 26)] = b2[t];
    }
    for (int i = t; i < NSTEP + 1; i += TPB) sTs[i] = t_span[i];
    __syncthreads();

    const int lane = t & 31;
    const int warp = t >> 5;
    const int pair = warp >> 1;      // 0 or 1
    const int half = warp & 1;       // 0 or 1 (warp-uniform!)
    const int barid = pair + 1;
    const int gid = blockIdx.x * 64 + pair * 32 + lane;   // sample id

    const unsigned colOff = (unsigned)half * 112u;        // 28 floats
    const unsigned aW1 = smem_addr(sW1) + colOff;
    const unsigned aW2 = smem_addr(sW2) + colOff;
    const unsigned aB1 = smem_addr(sB1h) + colOff;
    const unsigned aB2 = smem_addr(sB2h) + colOff;
    const unsigned aW3 = smem_addr(sW3) + (unsigned)half * 832u;     // 26 rows * 32B
    // h1 slab: this thread writes indices half*26 + (0..25), reads 0..49
    const unsigned aHrow = smem_addr(sH) + ((unsigned)pair * (32u * 57u) + (unsigned)lane * 57u) * 4u;
    const unsigned aHw = aHrow + (unsigned)half * 104u;   // 26 floats
    // k slab
    const unsigned aKbase = smem_addr(sK) + ((unsigned)pair * (2u * 32u * 9u)) * 4u
                          + (unsigned)lane * 36u;
    const unsigned aKw = aKbase + (unsigned)half * (32u * 36u);
    const unsigned aKr = aKbase + (unsigned)(half ^ 1) * (32u * 36u);

    float bb3[6];
    #pragma unroll
    for (int d = 0; d < 6; d++) bb3[d] = __ldg(b3 + d);

    float y[6];
    #pragma unroll
    for (int d = 0; d < 6; d++) y[d] = g_y0[gid * 6 + d];

    float yt[6], k[6], acc[6];

    #pragma unroll 1
    for (int stp = 0; stp < NSTEP; stp++) {
        const float dt = sTs[stp + 1] - sTs[stp];
        #pragma unroll
        for (int d = 0; d < 6; d++) yt[d] = y[d];
        #pragma unroll 1
        for (int st = 0; st < 4; st++) {
            // ---- layer 1: own 26-unit half of h1 ----
            u64 h[13];
            load13(aB1, h);
            #pragma unroll
            for (int d = 0; d < 6; d++) {
                u64 yd = pack_dup(yt[d]);
                u64 w[13];
                load13(aW1 + d * 224, w);
                #pragma unroll
                for (int p = 0; p < 13; p++) h[p] = ffma2(yd, w[p], h[p]);
            }
            pair_bar(barid);   // previous eval's h1 reads are complete
            #pragma unroll
            for (int p = 0; p < 13; p++) {
                float x, z;
                unpack2(h[p], x, z);
                stsf(aHw + (unsigned)(8 * p), fmaxf(x, 0.0f));
                stsf(aHw + (unsigned)(8 * p + 4), fmaxf(z, 0.0f));
            }
            pair_bar(barid);   // both halves of h1 visible

            // ---- layer 2: own 26-unit half of h2, all 50 inputs ----
            u64 g[13];
            load13(aB2, g);
            #pragma unroll 5
            for (int i = 0; i < 50; i++) {
                u64 m = pack_dup(ldsf(aHrow + (unsigned)(4 * i)));
                u64 w[13];
                load13(aW2 + i * 224, w);
                #pragma unroll
                for (int p = 0; p < 13; p++) g[p] = ffma2(m, w[p], g[p]);
            }

            // ---- layer 3: partial k over own 26 h2 units ----
            u64 o0 = 0ull, o1 = 0ull, o2 = 0ull;
            #pragma unroll
            for (int p = 0; p < 13; p++) {
                float x, z;
                unpack2(g[p], x, z);
                u64 m0 = pack_dup(fmaxf(x, 0.0f));
                u64 m1 = pack_dup(fmaxf(z, 0.0f));
                unsigned r = aW3 + (unsigned)(2 * p) * 32u;
                u64 w0, w1;
                lds2(r, w0, w1);
                u64 wl = lds1(r + 16);
                o0 = ffma2(m0, w0, o0); o1 = ffma2(m0, w1, o1); o2 = ffma2(m0, wl, o2);
                lds2(r + 32, w0, w1);
                wl = lds1(r + 48);
                o0 = ffma2(m1, w0, o0); o1 = ffma2(m1, w1, o1); o2 = ffma2(m1, wl, o2);
            }
            float kp[6];
            unpack2(o0, kp[0], kp[1]);
            unpack2(o1, kp[2], kp[3]);
            unpack2(o2, kp[4], kp[5]);
            #pragma unroll
            for (int d = 0; d < 6; d++) stsf(aKw + (unsigned)(4 * d), kp[d]);
            pair_bar(barid);   // partner's partial k visible
            #pragma unroll
            for (int d = 0; d < 6; d++)
                k[d] = (kp[d] + ldsf(aKr + (unsigned)(4 * d))) + bb3[d];  // commutative: identical in both warps

            if (st == 0) {
                #pragma unroll
                for (int d = 0; d < 6; d++) { acc[d] = k[d]; yt[d] = fmaf(0.5f * dt, k[d], y[d]); }
            } else if (st == 1) {
                #pragma unroll
                for (int d = 0; d < 6; d++) { acc[d] += 2.0f * k[d]; yt[d] = fmaf(0.5f * dt, k[d], y[d]); }
            } else if (st == 2) {
                #pragma unroll
                for (int d = 0; d < 6; d++) { acc[d] += 2.0f * k[d]; yt[d] = fmaf(dt, k[d], y[d]); }
            } else {
                #pragma unroll
                for (int d = 0; d < 6; d++) y[d] = fmaf(dt * (1.0f / 6.0f), acc[d] + k[d], y[d]);
            }
        }
    }

    if (half == 0) {
        #pragma unroll
        for (int d = 0; d < 6; d++) out[gid * 6 + d] = y[d];
    }
}

extern "C" void kernel_launch(void* const* d_in, const int* in_sizes, int n_in,
                              void* d_out, int out_size) {
    const float* x0 = (const float*)d_in[0];
    const float* ts = (const float*)d_in[1];
    const float* W1 = (const float*)d_in[2];
    const float* b1 = (const float*)d_in[3];
    const float* W2 = (const float*)d_in[4];
    const float* b2 = (const float*)d_in[5];
    const float* W3 = (const float*)d_in[6];
    const float* b3 = (const float*)d_in[7];
    float* out = (float*)d_out;

    mean_kernel<<<8192, 256>>>(x0);
    // 64 samples per block, 2 warps per 32 samples
    ode_kernel<<<B_TOTAL / 64, TPB>>>(ts, W1, b1, W2, b2, W3, b3, out);
}